// round 14
// baseline (speedup 1.0000x reference)
#include <cuda_runtime.h>

// x: (B=16, C=512, H=62, W=62) fp32, row-major.
// 9 regions: 2x2 patches at (y,x), y,x in {0,30,60}. flat base = y*62 + x.
// Patch elements: base, base+1, base+62, base+63. Pairs: (2k, 2k+1).
//
// Structure: one block per (pair, region) cell -> whole channel reduction is
// block-local; cross-block communication is a single fixed-point atomicAdd of
// the cell's log term. Tail = 1 REDG + ticket + 1 load.
#define HW      3844
#define WIDTH   62
#define CHN     512
#define NPAIR   8
#define NREG    9
#define NBLK    (NPAIR * NREG)     // 72 blocks
#define NWARP   (CHN / 32)         // 16 warps/block
#define EPSV    1e-6f
#define LSCALE  1099511627776.0    // 2^40 fixed-point scale for the log sum

__constant__ int c_posbase[9] = {0, 30, 60, 1860, 1890, 1920, 3720, 3750, 3780};
// region -> 5 negative region indices (region 8 = {2,4,5,6,7}; verified vs ref)
__constant__ int c_negidx[9][5] = {
    {1,3,4,2,6},
    {0,2,3,4,5},
    {0,1,4,5,8},
    {0,1,4,6,7},
    {0,1,3,5,7},
    {1,2,4,7,8},
    {0,3,4,7,8},
    {3,4,5,6,8},
    {2,4,5,6,7}
};

// Single fixed-point loss accumulator (integer: order-independent, deterministic)
// + ticket. Zero-init covers launch 1; last block re-zeros for graph replays.
__device__ unsigned long long g_loss;
__device__ unsigned int       g_count;

struct Patch { float a, b, c, d, ss; };

__device__ __forceinline__ Patch load_patch(const float* __restrict__ plane, int base) {
    // base always even -> 8-byte aligned float2 loads
    float2 v01 = *reinterpret_cast<const float2*>(plane + base);
    float2 v23 = *reinterpret_cast<const float2*>(plane + base + WIDTH);
    Patch p;
    p.a = v01.x; p.b = v01.y; p.c = v23.x; p.d = v23.y;
    p.ss = fmaf(p.a, p.a, fmaf(p.b, p.b, fmaf(p.c, p.c, p.d * p.d)));
    return p;
}

// exp(cos(p,q)/TEMP) with clamp cos = dot / max(na*nb, EPS); TEMP = 0.1
__device__ __forceinline__ float cexp(const Patch& p, const Patch& q) {
    float dot = fmaf(p.a, q.a, fmaf(p.b, q.b, fmaf(p.c, q.c, p.d * q.d)));
    float d2  = p.ss * q.ss;                  // (na*nb)^2
    float inv = rsqrtf(d2);
    float cosv = (d2 >= EPSV * EPSV) ? dot * inv : dot * (1.0f / EPSV);
    return __expf(cosv * 10.0f);
}

__global__ __launch_bounds__(CHN)
void lcl_cell(const float* __restrict__ x, float* __restrict__ out) {
    const int bid  = blockIdx.x;              // 0..71
    const int p    = bid / NREG;              // pair 0..7
    const int r    = bid - p * NREG;          // region 0..8
    const int tid  = threadIdx.x;             // channel 0..511
    const int wid  = tid >> 5;
    const int lane = tid & 31;

    __shared__ float sh[NWARP][3];
    __shared__ int   s_isLast;

    const float* p1 = x + ((size_t)(2 * p) * CHN + (size_t)tid) * HW;   // batch 2k
    const float* p2 = p1 + (size_t)CHN * HW;                            // batch 2k+1

    const int pb = c_posbase[r];
    const Patch a1 = load_patch(p1, pb);      // 24 independent LDG.64 total
    const Patch a2 = load_patch(p2, pb);

    float S  = cexp(a1, a2);
    float D1 = 0.0f, D2 = 0.0f;

#pragma unroll
    for (int n = 0; n < 5; n++) {
        const int nb = c_posbase[c_negidx[r][n]];
        const Patch b1 = load_patch(p1, nb);  // i1n patch
        const Patch b2 = load_patch(p2, nb);  // i2n patch
        D1 += cexp(a1, b1) + cexp(a1, b2);
        D2 += cexp(a2, b2) + cexp(a2, b1);
    }

#pragma unroll
    for (int o = 16; o; o >>= 1) {            // full warp active
        S  += __shfl_xor_sync(0xffffffffu, S,  o);
        D1 += __shfl_xor_sync(0xffffffffu, D1, o);
        D2 += __shfl_xor_sync(0xffffffffu, D2, o);
    }
    if (lane == 0) { sh[wid][0] = S; sh[wid][1] = D1; sh[wid][2] = D2; }
    __syncthreads();

    if (tid == 0) {
        float Sx = 0.0f, d1 = 0.0f, d2 = 0.0f;
#pragma unroll
        for (int w = 0; w < NWARP; w++) {     // 48 LDS, pipelined
            Sx += sh[w][0]; d1 += sh[w][1]; d2 += sh[w][2];
        }
        // log((S+D1)/S) + log((S+D2)/S), fused (arg in [1,~1e16]; range-safe).
        float v = logf(((Sx + d1) / Sx) * ((Sx + d2) / Sx));  // v >= 0
        // Deterministic fixed-point contribution; one REDG to a single scalar.
        atomicAdd(&g_loss, __double2ull_rn((double)v * LSCALE));
        __threadfence();                      // release before ticket
        s_isLast = (atomicAdd(&g_count, 1u) == NBLK - 1u);
    }
    __syncthreads();

    if (s_isLast && tid == 0) {
        __threadfence();                      // acquire
        unsigned long long u = __ldcg(&g_loss);
        out[0] = (float)((double)u * (1.0 / LSCALE) / 144.0); // /BATCH/NREG
        g_loss  = 0ull;                       // reset for next graph replay
        g_count = 0u;
    }
}

extern "C" void kernel_launch(void* const* d_in, const int* in_sizes, int n_in,
                              void* d_out, int out_size) {
    const float* x = (const float*)d_in[0];
    float* out = (float*)d_out;
    (void)in_sizes; (void)n_in; (void)out_size;

    lcl_cell<<<NBLK, CHN>>>(x, out);          // 72 blocks x 512 threads
}

// round 15
// speedup vs baseline: 2.5092x; 2.5092x over previous
#include <cuda_runtime.h>

// x: (B=16, C=512, H=62, W=62) fp32, row-major.
// 9 regions: 2x2 patches at (y,x), y,x in {0,30,60}. flat base = y*62 + x.
// Patch elements: base, base+1, base+62, base+63. Pairs: (2k, 2k+1).
//
// Final structure (best measured family): 128 blocks x 9 warps; warp = region,
// lane = channel; patches staged once per block in smem (4 LDG.64/thread —
// minimal gather chain); cross-block fold via ticket + 72-thread refold.
#define HW      3844
#define WIDTH   62
#define CHN     512
#define NPAIR   8
#define NREG    9
#define NCHUNK  16
#define NBLK    (NCHUNK * NPAIR)   // 128
#define NCELL   (NPAIR * NREG)     // 72
#define EPSV    1e-6f

__constant__ int c_posbase[9] = {0, 30, 60, 1860, 1890, 1920, 3720, 3750, 3780};
// region -> 5 negative region indices (region 8 = {2,4,5,6,7}; verified vs ref)
__constant__ int c_negidx[9][5] = {
    {1,3,4,2,6},
    {0,2,3,4,5},
    {0,1,4,5,8},
    {0,1,4,6,7},
    {0,1,3,5,7},
    {1,2,4,7,8},
    {0,3,4,7,8},
    {3,4,5,6,8},
    {2,4,5,6,7}
};

// Partials: [pair][chunk][region][{S,D1,D2}] — lane-0 writes 3 adjacent floats
// (single 32B sector). Fully overwritten every launch.
__device__ float        g_partial[NPAIR][NCHUNK][NREG][3];
__device__ unsigned int g_count;   // zero-init; last block resets each launch

struct Patch { float a, b, c, d, ss; };

__device__ __forceinline__ Patch load_patch(const float* __restrict__ plane, int base) {
    // base always even -> 8-byte aligned float2 loads
    float2 v01 = *reinterpret_cast<const float2*>(plane + base);
    float2 v23 = *reinterpret_cast<const float2*>(plane + base + WIDTH);
    Patch p;
    p.a = v01.x; p.b = v01.y; p.c = v23.x; p.d = v23.y;
    p.ss = fmaf(p.a, p.a, fmaf(p.b, p.b, fmaf(p.c, p.c, p.d * p.d)));
    return p;
}

// exp(cos(p,q)/TEMP) with clamp cos = dot / max(na*nb, EPS); TEMP = 0.1
__device__ __forceinline__ float cexp(const Patch& p, const Patch& q) {
    float dot = fmaf(p.a, q.a, fmaf(p.b, q.b, fmaf(p.c, q.c, p.d * q.d)));
    float d2  = p.ss * q.ss;                  // (na*nb)^2
    float inv = rsqrtf(d2);
    float cosv = (d2 >= EPSV * EPSV) ? dot * inv : dot * (1.0f / EPSV);
    return __expf(cosv * 10.0f);
}

__global__ __launch_bounds__(NREG * 32)
void lcl_fused(const float* __restrict__ x, float* __restrict__ out) {
    const int pair  = blockIdx.y;             // 0..7
    const int chunk = blockIdx.x;             // 0..15
    const int tid   = threadIdx.x;
    const int r     = tid >> 5;               // region = warp id, 0..8
    const int lane  = tid & 31;
    const int c     = chunk * 32 + lane;      // channel 0..511

    // Stage patches in smem: [plane][region][lane]; stride 5 words -> conflict-free
    __shared__ Patch shp[2][NREG][32];
    __shared__ float shv[NCELL];
    __shared__ int   s_isLast;

    {
        const float* p1 = x + ((size_t)(2 * pair) * CHN + (size_t)c) * HW;  // batch 2k
        const float* p2 = p1 + (size_t)CHN * HW;                            // batch 2k+1
        const int pb = c_posbase[r];
        shp[0][r][lane] = load_patch(p1, pb);   // each warp loads only its region
        shp[1][r][lane] = load_patch(p2, pb);
    }
    __syncthreads();

    const Patch a1 = shp[0][r][lane];
    const Patch a2 = shp[1][r][lane];

    float S  = cexp(a1, a2);
    float D1 = 0.0f, D2 = 0.0f;

#pragma unroll
    for (int n = 0; n < 5; n++) {
        const int j = c_negidx[r][n];
        const Patch b1 = shp[0][j][lane];     // i1n patch
        const Patch b2 = shp[1][j][lane];     // i2n patch
        D1 += cexp(a1, b1) + cexp(a1, b2);
        D2 += cexp(a2, b2) + cexp(a2, b1);
    }

#pragma unroll
    for (int o = 16; o; o >>= 1) {
        S  += __shfl_xor_sync(0xffffffffu, S,  o);   // full warp active
        D1 += __shfl_xor_sync(0xffffffffu, D1, o);
        D2 += __shfl_xor_sync(0xffffffffu, D2, o);
    }
    if (lane == 0) {
        g_partial[pair][chunk][r][0] = S;     // 3 adjacent floats: 1 sector
        g_partial[pair][chunk][r][1] = D1;
        g_partial[pair][chunk][r][2] = D2;
        __threadfence();                      // release partials before ticket
    }
    __syncthreads();

    if (tid == 0)
        s_isLast = (atomicAdd(&g_count, 1u) == NBLK - 1u);
    __syncthreads();

    if (s_isLast) {
        __threadfence();                      // acquire; block-uniform, no divergence
        // Final fold: 72 (pair,region) cells, 16 chunk-partials each, 48-way MLP.
        if (tid < NCELL) {                    // no sync primitives inside this guard
            const int p  = tid / NREG;
            const int rr = tid % NREG;
            float Sx = 0.0f, d1 = 0.0f, d2 = 0.0f;
#pragma unroll
            for (int ch = 0; ch < NCHUNK; ch++) {
                Sx += __ldcg(&g_partial[p][ch][rr][0]);
                d1 += __ldcg(&g_partial[p][ch][rr][1]);
                d2 += __ldcg(&g_partial[p][ch][rr][2]);
            }
            // log((S+D1)/S) + log((S+D2)/S) fused into one logf (range-safe:
            // argument in [1, ~1e16], well inside fp32).
            shv[tid] = logf(((Sx + d1) / Sx) * ((Sx + d2) / Sx));
        }
        __syncthreads();                      // block-uniform
        if (tid == 0) {
            float tot = 0.0f;
#pragma unroll
            for (int i = 0; i < NCELL; i++) tot += shv[i];
            out[0] = tot * (1.0f / 144.0f);   // / BATCH(16) / N_REGIONS(9)
            g_count = 0;                      // reset for next graph replay
        }
    }
}

extern "C" void kernel_launch(void* const* d_in, const int* in_sizes, int n_in,
                              void* d_out, int out_size) {
    const float* x = (const float*)d_in[0];
    float* out = (float*)d_out;
    (void)in_sizes; (void)n_in; (void)out_size;

    dim3 grid(NCHUNK, NPAIR, 1);              // 128 blocks, one wave
    dim3 block(NREG * 32, 1, 1);              // 288 threads = 9 warps (1 per region)
    lcl_fused<<<grid, block>>>(x, out);
}